// round 7
// baseline (speedup 1.0000x reference)
#include <cuda_runtime.h>
#include <math.h>
#include <float.h>
#include <stdint.h>

#define Bb 4
#define Nn 8192
#define Ss 2048
#define Kk 64
#define EPSf 1e-5f

#define FCTAS 4                  // 1 FPS CTA per batch
#define WCTAS 124                // persistent worker CTAs
#define GRID  (FCTAS + WCTAS)    // 128 CTAs, 1 CTA/SM, single wave
#define TPB   1024
#define NT    ((Bb*Ss)/4)        // worker tasks (4 centroids each)

typedef unsigned long long ull;

// ---------------- device scratch ----------------
__device__ float g_cen[Bb*Ss*3];
__device__ int   g_prog[Bb];
__device__ float g_wf1[64*67];
__device__ float g_bf1[64];
__device__ float g_wf2[64*64];
__device__ float g_bf2[64];
__device__ float g_wf3[128*64];
__device__ float g_bf3[128];

// ---------------- packed f32x2 helpers (per-lane rn == scalar rn) ----------------
__device__ __forceinline__ ull pk2(float lo, float hi) {
    ull r; asm("mov.b64 %0, {%1, %2};" : "=l"(r) : "f"(lo), "f"(hi)); return r;
}
__device__ __forceinline__ void up2(ull v, float& a, float& b) {
    asm("mov.b64 {%0, %1}, %2;" : "=f"(a), "=f"(b) : "l"(v));
}
__device__ __forceinline__ ull add2(ull a, ull b) {
    ull r; asm("add.rn.f32x2 %0, %1, %2;" : "=l"(r) : "l"(a), "l"(b)); return r;
}
__device__ __forceinline__ ull mul2(ull a, ull b) {
    ull r; asm("mul.rn.f32x2 %0, %1, %2;" : "=l"(r) : "l"(a), "l"(b)); return r;
}

__device__ __forceinline__ int ld_acquire_gpu(const int* p) {
    int v; asm volatile("ld.acquire.gpu.global.s32 %0, [%1];" : "=r"(v) : "l"(p) : "memory");
    return v;
}
__device__ __forceinline__ void st_release_gpu(int* p, int v) {
    asm volatile("st.release.gpu.global.s32 [%0], %1;" :: "l"(p), "r"(v) : "memory");
}

// ---------------- fold BN into conv + reset progress ----------------
__global__ void fold_kernel(
    const float* W1, const float* b1, const float* g1, const float* bt1, const float* m1, const float* v1,
    const float* W2, const float* b2, const float* g2, const float* bt2, const float* m2, const float* v2,
    const float* W3, const float* b3, const float* g3, const float* bt3, const float* m3, const float* v3)
{
    int t = threadIdx.x;
    for (int i = t; i < 64*67; i += blockDim.x) {
        int o = i / 67;
        g_wf1[i] = W1[i] * (g1[o] * rsqrtf(v1[o] + EPSf));
    }
    for (int i = t; i < 64; i += blockDim.x)
        g_bf1[i] = (b1[i] - m1[i]) * (g1[i] * rsqrtf(v1[i] + EPSf)) + bt1[i];
    for (int i = t; i < 64*64; i += blockDim.x) {
        int o = i >> 6;
        g_wf2[i] = W2[i] * (g2[o] * rsqrtf(v2[o] + EPSf));
    }
    for (int i = t; i < 64; i += blockDim.x)
        g_bf2[i] = (b2[i] - m2[i]) * (g2[i] * rsqrtf(v2[i] + EPSf)) + bt2[i];
    for (int i = t; i < 128*64; i += blockDim.x) {
        int o = i >> 6;
        g_wf3[i] = W3[i] * (g3[o] * rsqrtf(v3[o] + EPSf));
    }
    for (int i = t; i < 128; i += blockDim.x)
        g_bf3[i] = (b3[i] - m3[i]) * (g3[i] * rsqrtf(v3[i] + EPSf)) + bt3[i];

    if (t < Bb) g_prog[t] = 0;
}

// ---------------- shared-memory layout (floats) : worker view ----------------
#define OW1 0
#define OB1 (OW1 + 64*67)
#define OW2 (OB1 + 64)
#define OB2 (OW2 + 64*65)
#define OW3 (OB2 + 64)
#define OB3 (OW3 + 128*65)
#define OBUF (OB3 + 128)
#define GRP  (67*65 + 64*65)
#define OIDXA (OBUF + 4*GRP)
#define SMEM_FLOATS (OIDXA + 4*64)
#define SMEM_BYTES  (SMEM_FLOATS * 4)
// fps view: float4 coords [Nn] then 3 x u64 best slots
#define F_BEST (4*Nn)            // float offset of best[3] (16B-aligned)

// =====================================================================
// persistent kernel, single launch, no clusters:
//   CTA 0..3   : FPS for batch = blockIdx.x (1024 thr, all 2048 steps)
//   CTA 4..127 : workers; consume centroids via g_prog (release/acquire)
// =====================================================================
__global__ void __launch_bounds__(TPB, 1)
pipe_kernel(const float* __restrict__ x, const float* __restrict__ xc,
            float* __restrict__ out)
{
    extern __shared__ float sm[];
    const int tid  = threadIdx.x;
    const int lane = tid & 31;

    if (blockIdx.x < FCTAS) {
        // ================= FPS (single CTA per batch) =================
        const int b = blockIdx.x;
        const float* xb = x + (size_t)b * Nn * 3;

        float4* sc4 = (float4*)sm;                 // [Nn] staged coords
        ull*    best = (ull*)(sm + F_BEST);        // [3] parity slots

        // stage coords once (persistent -> amortized over all 2048 steps)
        for (int i = tid; i < Nn; i += TPB) {
            float4 v;
            v.x = xb[i*3 + 0];
            v.y = xb[i*3 + 1];
            v.z = xb[i*3 + 2];
            v.w = 0.f;
            sc4[i] = v;
        }
        if (tid < 3) best[tid] = 0ull;

        // 8 points per thread (4 packed pairs); static reg indexing only
        ull px[4], py[4], pz[4];
        float dist[8];
#pragma unroll
        for (int i = 0; i < 4; i++) {
            int p = tid * 8 + i * 2;
            px[i] = pk2(xb[p*3 + 0], xb[p*3 + 3]);
            py[i] = pk2(xb[p*3 + 1], xb[p*3 + 4]);
            pz[i] = pk2(xb[p*3 + 2], xb[p*3 + 5]);
        }
#pragma unroll
        for (int j = 0; j < 8; j++) dist[j] = 1e10f;

        int cur = 0;
        int par = 0;
        int* progp = &g_prog[b];
        __syncthreads();   // coords staged + best slots zeroed

        for (int s = 0; s < Ss; s++) {
            const int parN = (par == 2) ? 0 : par + 1;

            // uniform broadcast centroid read (1 x LDS.128)
            const float4 c4 = sc4[cur];
            const float cx = c4.x, cy = c4.y, cz = c4.z;
            if (tid == 0) {
                int oc = (b*Ss + s) * 3;
                g_cen[oc+0] = cx; g_cen[oc+1] = cy; g_cen[oc+2] = cz;
                out[oc+0]  = cx; out[oc+1]  = cy; out[oc+2]  = cz;
                if ((s & 31) == 31) st_release_gpu(progp, s + 1);
            }
            // recycle the slot for step s+1 (its readers all finished before
            // barrier s-1; its next writers start after barrier s) -> race-free
            if (tid == 64) best[parN] = 0ull;

            const ull ncx = pk2(-cx, -cx);
            const ull ncy = pk2(-cy, -cy);
            const ull ncz = pk2(-cz, -cz);

            float mm[4];
#pragma unroll
            for (int i = 0; i < 4; i++) {
                ull dx = add2(px[i], ncx);
                ull dy = add2(py[i], ncy);
                ull dz = add2(pz[i], ncz);
                ull dd = add2(add2(mul2(dx,dx), mul2(dy,dy)), mul2(dz,dz));
                float d0, d1; up2(dd, d0, d1);
                float n0 = fminf(dist[2*i],   d0);
                float n1 = fminf(dist[2*i+1], d1);
                dist[2*i] = n0; dist[2*i+1] = n1;
                mm[i] = fmaxf(n0, n1);
            }
            float bestv = fmaxf(fmaxf(mm[0], mm[1]), fmaxf(mm[2], mm[3]));

            // warp argmax: max dist bits (all >=0), min matching index on ties
            unsigned mv   = __float_as_uint(bestv);
            unsigned wmax = __reduce_max_sync(0xffffffffu, mv);
            unsigned loc  = 0xffffffffu;
            if (mv == wmax) {
                float fm = __uint_as_float(wmax);
#pragma unroll
                for (int j = 7; j >= 0; j--)
                    if (dist[j] == fm) loc = (unsigned)(tid*8 + j);  // ends at smallest j
            }
            unsigned widx = __reduce_min_sync(0xffffffffu, loc);

            // block combine: one packed 64-bit atomicMax per warp
            // key = (distbits << 32) | ~idx  ->  max dist, tie -> min index
            if (lane == 0) {
                ull key = ((ull)wmax << 32) | (ull)(~widx);
                atomicMax(&best[par], key);
            }
            __syncthreads();   // single barrier per step

            ull k = best[par];
            cur = (int)(~(unsigned)k);
            par = parN;
        }
        return;
    }

    // ================= persistent worker: ball query + MLP =================
    const int widx_ = blockIdx.x - FCTAS;

    for (int i = tid; i < 64*67; i += TPB) sm[OW1 + i] = g_wf1[i];
    for (int i = tid; i < 64*64; i += TPB) {
        int o = i >> 6, c = i & 63;
        sm[OW2 + o*65 + c] = g_wf2[i];
    }
    for (int i = tid; i < 128*64; i += TPB) {
        int o = i >> 6, c = i & 63;
        sm[OW3 + o*65 + c] = g_wf3[i];
    }
    for (int i = tid; i < 64;  i += TPB) { sm[OB1+i] = g_bf1[i]; sm[OB2+i] = g_bf2[i]; }
    for (int i = tid; i < 128; i += TPB) sm[OB3 + i] = g_bf3[i];

    float* pooled = out + (size_t)Bb * Ss * 3;

    // 4 groups of 256 threads; one centroid per group
    const int wgid    = tid >> 8;        // 0..3
    const int wg_tid  = tid & 255;
    const int tx      = wg_tid & 31;     // 2 k-cols each
    const int ty      = wg_tid >> 5;     // 8 out-rows each (0..7)

    for (int t = widx_; t < NT; t += WCTAS) {
        const int b  = t & 3;
        const int s0 = (t >> 2) * 4;

        if (tid == 0) {
            while (ld_acquire_gpu(&g_prog[b]) < s0 + 4) __nanosleep(128);
        }
        __syncthreads();   // progress visible + previous task's buffers free

        // ---- ball query: first warp of each group, one centroid each ----
        if (ty == 0) {
            const int cen = b * Ss + s0 + wgid;
            const float cx = g_cen[cen*3 + 0];
            const float cy = g_cen[cen*3 + 1];
            const float cz = g_cen[cen*3 + 2];
            const float* xb = x + (size_t)b * Nn * 3;
            int* outp = (int*)&sm[OIDXA + wgid*64];

            int count = 0;
            for (int base = 0; base < Nn && count < Kk; base += 32) {
                int p = base + lane;
                float qx = xb[p*3 + 0], qy = xb[p*3 + 1], qz = xb[p*3 + 2];
                float dx = __fsub_rn(cx, qx);
                float dy = __fsub_rn(cy, qy);
                float dz = __fsub_rn(cz, qz);
                float d  = __fadd_rn(__fadd_rn(__fmul_rn(dx,dx), __fmul_rn(dy,dy)),
                                     __fmul_rn(dz,dz));
                bool hit = d < 0.04f;
                unsigned m = __ballot_sync(0xffffffffu, hit);
                int rk = __popc(m & ((1u << lane) - 1u));
                if (hit && (count + rk) < Kk) outp[count + rk] = p;
                count += __popc(m);
            }
            count = min(count, Kk);
            for (int q = count + lane; q < Kk; q += 32) outp[q] = -1;
        }
        __syncthreads();

        const int cen = b * Ss + s0 + wgid;
        const int OF = OBUF + wgid * GRP;   // F [67][65]
        const int OH = OF + 67*65;          // H [64][65]
        int* sidx = (int*)&sm[OIDXA + wgid*64];

        // ---- gather: 8 warps per group, 8 ks per warp ----
        const float* xcb = xc + (size_t)b * Nn * 64;
        const float* xb  = x  + (size_t)b * Nn * 3;
        for (int kk = 0; kk < 8; kk++) {
            int k  = ty * 8 + kk;
            int gi = sidx[k];
            gi = gi < 0 ? 0 : gi;
            const float* row = xcb + (size_t)gi * 64;
            sm[OF + lane*65 + k]      = row[lane];
            sm[OF + (lane+32)*65 + k] = row[lane + 32];
            if (lane < 3)
                sm[OF + (64+lane)*65 + k] = xb[gi*3 + lane] - g_cen[cen*3 + lane];
        }
        __syncthreads();

        float acc[8][2];

        // ---- layer 1: H = relu(W1f @ F + b1f) ----
#pragma unroll
        for (int i = 0; i < 8; i++)
#pragma unroll
            for (int j = 0; j < 2; j++) acc[i][j] = 0.f;
        for (int c = 0; c < 67; c++) {
            float fv[2];
#pragma unroll
            for (int j = 0; j < 2; j++) fv[j] = sm[OF + c*65 + tx*2 + j];
#pragma unroll
            for (int i = 0; i < 8; i++) {
                float wv = sm[OW1 + (ty*8 + i)*67 + c];
#pragma unroll
                for (int j = 0; j < 2; j++) acc[i][j] = fmaf(wv, fv[j], acc[i][j]);
            }
        }
#pragma unroll
        for (int i = 0; i < 8; i++) {
            float bia = sm[OB1 + ty*8 + i];
#pragma unroll
            for (int j = 0; j < 2; j++)
                sm[OH + (ty*8 + i)*65 + tx*2 + j] = fmaxf(acc[i][j] + bia, 0.f);
        }
        __syncthreads();

        // ---- layer 2 (into F buffer) ----
#pragma unroll
        for (int i = 0; i < 8; i++)
#pragma unroll
            for (int j = 0; j < 2; j++) acc[i][j] = 0.f;
        for (int c = 0; c < 64; c++) {
            float fv[2];
#pragma unroll
            for (int j = 0; j < 2; j++) fv[j] = sm[OH + c*65 + tx*2 + j];
#pragma unroll
            for (int i = 0; i < 8; i++) {
                float wv = sm[OW2 + (ty*8 + i)*65 + c];
#pragma unroll
                for (int j = 0; j < 2; j++) acc[i][j] = fmaf(wv, fv[j], acc[i][j]);
            }
        }
#pragma unroll
        for (int i = 0; i < 8; i++) {
            float bia = sm[OB2 + ty*8 + i];
#pragma unroll
            for (int j = 0; j < 2; j++)
                sm[OF + (ty*8 + i)*65 + tx*2 + j] = fmaxf(acc[i][j] + bia, 0.f);
        }
        __syncthreads();

        // ---- layer 3 (128 outs, two 64-row passes) + masked maxpool ----
        for (int op = 0; op < 2; op++) {
#pragma unroll
            for (int i = 0; i < 8; i++)
#pragma unroll
                for (int j = 0; j < 2; j++) acc[i][j] = 0.f;
            for (int c = 0; c < 64; c++) {
                float fv[2];
#pragma unroll
                for (int j = 0; j < 2; j++) fv[j] = sm[OF + c*65 + tx*2 + j];
#pragma unroll
                for (int i = 0; i < 8; i++) {
                    float wv = sm[OW3 + (op*64 + ty*8 + i)*65 + c];
#pragma unroll
                    for (int j = 0; j < 2; j++) acc[i][j] = fmaf(wv, fv[j], acc[i][j]);
                }
            }
#pragma unroll
            for (int i = 0; i < 8; i++) {
                int o = op*64 + ty*8 + i;
                float bia = sm[OB3 + o];
                float m = -INFINITY;
#pragma unroll
                for (int j = 0; j < 2; j++) {
                    int k = tx*2 + j;
                    float v = fmaxf(acc[i][j] + bia, 0.f);
                    if (sidx[k] >= 0) m = fmaxf(m, v);
                }
                // reduce across the 32 tx lanes (full warp)
#pragma unroll
                for (int off = 16; off; off >>= 1)
                    m = fmaxf(m, __shfl_xor_sync(0xffffffffu, m, off));
                if (tx == 0) pooled[(size_t)cen * 128 + o] = m;
            }
        }
    }
}

// ---------------- launch ----------------
extern "C" void kernel_launch(void* const* d_in, const int* in_sizes, int n_in,
                              void* d_out, int out_size)
{
    const float* x   = (const float*)d_in[0];
    const float* xc  = (const float*)d_in[1];
    const float* W1  = (const float*)d_in[2];
    const float* b1  = (const float*)d_in[3];
    const float* g1  = (const float*)d_in[4];
    const float* bt1 = (const float*)d_in[5];
    const float* m1  = (const float*)d_in[6];
    const float* v1  = (const float*)d_in[7];
    const float* W2  = (const float*)d_in[8];
    const float* b2  = (const float*)d_in[9];
    const float* g2  = (const float*)d_in[10];
    const float* bt2 = (const float*)d_in[11];
    const float* m2  = (const float*)d_in[12];
    const float* v2  = (const float*)d_in[13];
    const float* W3  = (const float*)d_in[14];
    const float* b3  = (const float*)d_in[15];
    const float* g3  = (const float*)d_in[16];
    const float* bt3 = (const float*)d_in[17];
    const float* m3  = (const float*)d_in[18];
    const float* v3  = (const float*)d_in[19];
    float* out = (float*)d_out;

    fold_kernel<<<1, 256>>>(W1,b1,g1,bt1,m1,v1, W2,b2,g2,bt2,m2,v2, W3,b3,g3,bt3,m3,v3);

    cudaFuncSetAttribute(pipe_kernel, cudaFuncAttributeMaxDynamicSharedMemorySize, SMEM_BYTES);
    pipe_kernel<<<GRID, TPB, SMEM_BYTES>>>(x, xc, out);
}

// round 8
// speedup vs baseline: 1.0592x; 1.0592x over previous
#include <cuda_runtime.h>
#include <math.h>
#include <float.h>
#include <stdint.h>

#define Bb 4
#define Nn 8192
#define Ss 2048
#define Kk 64
#define EPSf 1e-5f

#define FCTAS 4                  // 1 FPS CTA per batch
#define WCTAS 124                // persistent worker CTAs
#define GRID  (FCTAS + WCTAS)    // 128 CTAs, 1 CTA/SM, single wave
#define TPB   1024
#define NT    ((Bb*Ss)/4)        // worker tasks (4 centroids each)

typedef unsigned long long ull;

// ---------------- device scratch ----------------
__device__ float g_cen[Bb*Ss*3];
__device__ int   g_prog[Bb];
__device__ float g_wf1[64*67];
__device__ float g_bf1[64];
__device__ float g_wf2[64*64];
__device__ float g_bf2[64];
__device__ float g_wf3[128*64];
__device__ float g_bf3[128];

// ---------------- packed f32x2 helpers (per-lane rn == scalar rn) ----------------
__device__ __forceinline__ ull pk2(float lo, float hi) {
    ull r; asm("mov.b64 %0, {%1, %2};" : "=l"(r) : "f"(lo), "f"(hi)); return r;
}
__device__ __forceinline__ void up2(ull v, float& a, float& b) {
    asm("mov.b64 {%0, %1}, %2;" : "=f"(a), "=f"(b) : "l"(v));
}
__device__ __forceinline__ ull add2(ull a, ull b) {
    ull r; asm("add.rn.f32x2 %0, %1, %2;" : "=l"(r) : "l"(a), "l"(b)); return r;
}
__device__ __forceinline__ ull mul2(ull a, ull b) {
    ull r; asm("mul.rn.f32x2 %0, %1, %2;" : "=l"(r) : "l"(a), "l"(b)); return r;
}

__device__ __forceinline__ int ld_acquire_gpu(const int* p) {
    int v; asm volatile("ld.acquire.gpu.global.s32 %0, [%1];" : "=r"(v) : "l"(p) : "memory");
    return v;
}
__device__ __forceinline__ void st_release_gpu(int* p, int v) {
    asm volatile("st.release.gpu.global.s32 [%0], %1;" :: "l"(p), "r"(v) : "memory");
}

// ---------------- fold BN into conv + reset progress ----------------
__global__ void fold_kernel(
    const float* W1, const float* b1, const float* g1, const float* bt1, const float* m1, const float* v1,
    const float* W2, const float* b2, const float* g2, const float* bt2, const float* m2, const float* v2,
    const float* W3, const float* b3, const float* g3, const float* bt3, const float* m3, const float* v3)
{
    int t = threadIdx.x;
    for (int i = t; i < 64*67; i += blockDim.x) {
        int o = i / 67;
        g_wf1[i] = W1[i] * (g1[o] * rsqrtf(v1[o] + EPSf));
    }
    for (int i = t; i < 64; i += blockDim.x)
        g_bf1[i] = (b1[i] - m1[i]) * (g1[i] * rsqrtf(v1[i] + EPSf)) + bt1[i];
    for (int i = t; i < 64*64; i += blockDim.x) {
        int o = i >> 6;
        g_wf2[i] = W2[i] * (g2[o] * rsqrtf(v2[o] + EPSf));
    }
    for (int i = t; i < 64; i += blockDim.x)
        g_bf2[i] = (b2[i] - m2[i]) * (g2[i] * rsqrtf(v2[i] + EPSf)) + bt2[i];
    for (int i = t; i < 128*64; i += blockDim.x) {
        int o = i >> 6;
        g_wf3[i] = W3[i] * (g3[o] * rsqrtf(v3[o] + EPSf));
    }
    for (int i = t; i < 128; i += blockDim.x)
        g_bf3[i] = (b3[i] - m3[i]) * (g3[i] * rsqrtf(v3[i] + EPSf)) + bt3[i];

    if (t < Bb) g_prog[t] = 0;
}

// ---------------- shared-memory layout (floats) : worker view ----------------
#define OW1 0
#define OB1 (OW1 + 64*67)
#define OW2 (OB1 + 64)
#define OB2 (OW2 + 64*65)
#define OW3 (OB2 + 64)
#define OB3 (OW3 + 128*65)
#define OBUF (OB3 + 128)
#define GRP  (67*65 + 64*65)
#define OIDXA (OBUF + 4*GRP)
#define SMEM_FLOATS (OIDXA + 4*64)
#define SMEM_BYTES  (SMEM_FLOATS * 4)
// fps view (same dynamic buffer)
#define F_SX   0
#define F_SY   Nn
#define F_SZ   (2*Nn)
#define F_SVAL (3*Nn)            // [2][32] u32
#define F_SIDX (3*Nn + 64)       // [2][32] u32

// =====================================================================
// persistent kernel, single launch, no clusters:
//   CTA 0..3   : FPS for batch = blockIdx.x (1024 thr, all 2048 steps)
//   CTA 4..127 : workers; consume centroids via g_prog (release/acquire)
// =====================================================================
__global__ void __launch_bounds__(TPB, 1)
pipe_kernel(const float* __restrict__ x, const float* __restrict__ xc,
            float* __restrict__ out)
{
    extern __shared__ float sm[];
    const int tid  = threadIdx.x;
    const int lane = tid & 31;
    const int wrp  = tid >> 5;

    if (blockIdx.x < FCTAS) {
        // ================= FPS (single CTA per batch) =================
        const int b = blockIdx.x;
        const float* xb = x + (size_t)b * Nn * 3;

        float* sx = sm + F_SX;
        float* sy = sm + F_SY;
        float* sz = sm + F_SZ;
        unsigned* svalA = (unsigned*)(sm + F_SVAL);
        unsigned* sidxA = (unsigned*)(sm + F_SIDX);

        // stage coords once (persistent -> amortized over all 2048 steps)
        for (int i = tid; i < Nn; i += TPB) {
            sx[i] = xb[i*3 + 0];
            sy[i] = xb[i*3 + 1];
            sz[i] = xb[i*3 + 2];
        }

        // 8 points per thread (4 packed pairs); static reg indexing only
        ull px[4], py[4], pz[4];
        float dist[8];
#pragma unroll
        for (int i = 0; i < 4; i++) {
            int p = tid * 8 + i * 2;
            px[i] = pk2(xb[p*3 + 0], xb[p*3 + 3]);
            py[i] = pk2(xb[p*3 + 1], xb[p*3 + 4]);
            pz[i] = pk2(xb[p*3 + 2], xb[p*3 + 5]);
        }
#pragma unroll
        for (int j = 0; j < 8; j++) dist[j] = 1e10f;

        int cur = 0;
        int* progp = &g_prog[b];
        __syncthreads();   // coords staged

        for (int s = 0; s < Ss; s++) {
            const int par = s & 1;
            // uniform broadcast centroid read
            const float cx = sx[cur];
            const float cy = sy[cur];
            const float cz = sz[cur];
            if (tid == 0) {
                int oc = (b*Ss + s) * 3;
                g_cen[oc+0] = cx; g_cen[oc+1] = cy; g_cen[oc+2] = cz;
                out[oc+0]  = cx; out[oc+1]  = cy; out[oc+2]  = cz;
                if ((s & 15) == 15) st_release_gpu(progp, s + 1);
            }

            const ull ncx = pk2(-cx, -cx);
            const ull ncy = pk2(-cy, -cy);
            const ull ncz = pk2(-cz, -cz);

            // incremental per-thread argmax (lowest index wins all ties)
            float bv = -1.0f;
            int   bj = 0;
#pragma unroll
            for (int i = 0; i < 4; i++) {
                ull dx = add2(px[i], ncx);
                ull dy = add2(py[i], ncy);
                ull dz = add2(pz[i], ncz);
                ull dd = add2(add2(mul2(dx,dx), mul2(dy,dy)), mul2(dz,dz));
                float d0, d1; up2(dd, d0, d1);
                float n0 = fminf(dist[2*i],   d0);
                float n1 = fminf(dist[2*i+1], d1);
                dist[2*i] = n0; dist[2*i+1] = n1;
                float vp = fmaxf(n0, n1);
                int   jp = (n0 >= n1) ? (2*i) : (2*i + 1);   // tie -> lower j
                if (vp > bv) { bv = vp; bj = jp; }           // strict > keeps lower j
            }

            // warp argmax: redux max on dist bits (all >= 0), then lowest
            // matching lane (lowest lane => lowest tid => lowest global index)
            unsigned mv   = __float_as_uint(bv);
            unsigned wmax = __reduce_max_sync(0xffffffffu, mv);
            unsigned ball = __ballot_sync(0xffffffffu, mv == wmax);
            int src = __ffs((int)ball) - 1;
            unsigned widx = __shfl_sync(0xffffffffu, (unsigned)(tid*8 + bj), src);

            unsigned* sval = svalA + par*32;
            unsigned* sidx = sidxA + par*32;
            if (lane == 0) { sval[wrp] = wmax; sidx[wrp] = widx; }
            __syncthreads();   // one barrier per step (parity buffers avoid WAR)

            // every warp redundantly reduces the 32 warp results
            unsigned v  = sval[lane];
            unsigned id = sidx[lane];
            unsigned M  = __reduce_max_sync(0xffffffffu, v);
            unsigned cn = (v == M) ? id : 0xffffffffu;
            cur = (int)__reduce_min_sync(0xffffffffu, cn);
        }
        return;
    }

    // ================= persistent worker: ball query + MLP =================
    const int widx_ = blockIdx.x - FCTAS;

    for (int i = tid; i < 64*67; i += TPB) sm[OW1 + i] = g_wf1[i];
    for (int i = tid; i < 64*64; i += TPB) {
        int o = i >> 6, c = i & 63;
        sm[OW2 + o*65 + c] = g_wf2[i];
    }
    for (int i = tid; i < 128*64; i += TPB) {
        int o = i >> 6, c = i & 63;
        sm[OW3 + o*65 + c] = g_wf3[i];
    }
    for (int i = tid; i < 64;  i += TPB) { sm[OB1+i] = g_bf1[i]; sm[OB2+i] = g_bf2[i]; }
    for (int i = tid; i < 128; i += TPB) sm[OB3 + i] = g_bf3[i];

    float* pooled = out + (size_t)Bb * Ss * 3;

    // 4 groups of 256 threads; one centroid per group
    const int wgid    = tid >> 8;        // 0..3
    const int wg_tid  = tid & 255;
    const int tx      = wg_tid & 31;     // 2 k-cols each
    const int ty      = wg_tid >> 5;     // 8 out-rows each (0..7)

    for (int t = widx_; t < NT; t += WCTAS) {
        const int b  = t & 3;
        const int s0 = (t >> 2) * 4;

        if (tid == 0) {
            while (ld_acquire_gpu(&g_prog[b]) < s0 + 4) __nanosleep(128);
        }
        __syncthreads();   // progress visible + previous task's buffers free

        // ---- ball query: first warp of each group, one centroid each ----
        if (ty == 0) {
            const int cen = b * Ss + s0 + wgid;
            const float cx = g_cen[cen*3 + 0];
            const float cy = g_cen[cen*3 + 1];
            const float cz = g_cen[cen*3 + 2];
            const float* xb = x + (size_t)b * Nn * 3;
            int* outp = (int*)&sm[OIDXA + wgid*64];

            int count = 0;
            for (int base = 0; base < Nn && count < Kk; base += 32) {
                int p = base + lane;
                float qx = xb[p*3 + 0], qy = xb[p*3 + 1], qz = xb[p*3 + 2];
                float dx = __fsub_rn(cx, qx);
                float dy = __fsub_rn(cy, qy);
                float dz = __fsub_rn(cz, qz);
                float d  = __fadd_rn(__fadd_rn(__fmul_rn(dx,dx), __fmul_rn(dy,dy)),
                                     __fmul_rn(dz,dz));
                bool hit = d < 0.04f;
                unsigned m = __ballot_sync(0xffffffffu, hit);
                int rk = __popc(m & ((1u << lane) - 1u));
                if (hit && (count + rk) < Kk) outp[count + rk] = p;
                count += __popc(m);
            }
            count = min(count, Kk);
            for (int q = count + lane; q < Kk; q += 32) outp[q] = -1;
        }
        __syncthreads();

        const int cen = b * Ss + s0 + wgid;
        const int OF = OBUF + wgid * GRP;   // F [67][65]
        const int OH = OF + 67*65;          // H [64][65]
        int* sidx = (int*)&sm[OIDXA + wgid*64];

        // ---- gather: 8 warps per group, 8 ks per warp ----
        const float* xcb = xc + (size_t)b * Nn * 64;
        const float* xb  = x  + (size_t)b * Nn * 3;
        for (int kk = 0; kk < 8; kk++) {
            int k  = ty * 8 + kk;
            int gi = sidx[k];
            gi = gi < 0 ? 0 : gi;
            const float* row = xcb + (size_t)gi * 64;
            sm[OF + lane*65 + k]      = row[lane];
            sm[OF + (lane+32)*65 + k] = row[lane + 32];
            if (lane < 3)
                sm[OF + (64+lane)*65 + k] = xb[gi*3 + lane] - g_cen[cen*3 + lane];
        }
        __syncthreads();

        float acc[8][2];

        // ---- layer 1: H = relu(W1f @ F + b1f) ----
#pragma unroll
        for (int i = 0; i < 8; i++)
#pragma unroll
            for (int j = 0; j < 2; j++) acc[i][j] = 0.f;
        for (int c = 0; c < 67; c++) {
            float fv[2];
#pragma unroll
            for (int j = 0; j < 2; j++) fv[j] = sm[OF + c*65 + tx*2 + j];
#pragma unroll
            for (int i = 0; i < 8; i++) {
                float wv = sm[OW1 + (ty*8 + i)*67 + c];
#pragma unroll
                for (int j = 0; j < 2; j++) acc[i][j] = fmaf(wv, fv[j], acc[i][j]);
            }
        }
#pragma unroll
        for (int i = 0; i < 8; i++) {
            float bia = sm[OB1 + ty*8 + i];
#pragma unroll
            for (int j = 0; j < 2; j++)
                sm[OH + (ty*8 + i)*65 + tx*2 + j] = fmaxf(acc[i][j] + bia, 0.f);
        }
        __syncthreads();

        // ---- layer 2 (into F buffer) ----
#pragma unroll
        for (int i = 0; i < 8; i++)
#pragma unroll
            for (int j = 0; j < 2; j++) acc[i][j] = 0.f;
        for (int c = 0; c < 64; c++) {
            float fv[2];
#pragma unroll
            for (int j = 0; j < 2; j++) fv[j] = sm[OH + c*65 + tx*2 + j];
#pragma unroll
            for (int i = 0; i < 8; i++) {
                float wv = sm[OW2 + (ty*8 + i)*65 + c];
#pragma unroll
                for (int j = 0; j < 2; j++) acc[i][j] = fmaf(wv, fv[j], acc[i][j]);
            }
        }
#pragma unroll
        for (int i = 0; i < 8; i++) {
            float bia = sm[OB2 + ty*8 + i];
#pragma unroll
            for (int j = 0; j < 2; j++)
                sm[OF + (ty*8 + i)*65 + tx*2 + j] = fmaxf(acc[i][j] + bia, 0.f);
        }
        __syncthreads();

        // ---- layer 3 (128 outs, two 64-row passes) + masked maxpool ----
        for (int op = 0; op < 2; op++) {
#pragma unroll
            for (int i = 0; i < 8; i++)
#pragma unroll
                for (int j = 0; j < 2; j++) acc[i][j] = 0.f;
            for (int c = 0; c < 64; c++) {
                float fv[2];
#pragma unroll
                for (int j = 0; j < 2; j++) fv[j] = sm[OF + c*65 + tx*2 + j];
#pragma unroll
                for (int i = 0; i < 8; i++) {
                    float wv = sm[OW3 + (op*64 + ty*8 + i)*65 + c];
#pragma unroll
                    for (int j = 0; j < 2; j++) acc[i][j] = fmaf(wv, fv[j], acc[i][j]);
                }
            }
#pragma unroll
            for (int i = 0; i < 8; i++) {
                int o = op*64 + ty*8 + i;
                float bia = sm[OB3 + o];
                float m = -INFINITY;
#pragma unroll
                for (int j = 0; j < 2; j++) {
                    int k = tx*2 + j;
                    float v = fmaxf(acc[i][j] + bia, 0.f);
                    if (sidx[k] >= 0) m = fmaxf(m, v);
                }
                // reduce across the 32 tx lanes (full warp)
#pragma unroll
                for (int off = 16; off; off >>= 1)
                    m = fmaxf(m, __shfl_xor_sync(0xffffffffu, m, off));
                if (tx == 0) pooled[(size_t)cen * 128 + o] = m;
            }
        }
    }
}

// ---------------- launch ----------------
extern "C" void kernel_launch(void* const* d_in, const int* in_sizes, int n_in,
                              void* d_out, int out_size)
{
    const float* x   = (const float*)d_in[0];
    const float* xc  = (const float*)d_in[1];
    const float* W1  = (const float*)d_in[2];
    const float* b1  = (const float*)d_in[3];
    const float* g1  = (const float*)d_in[4];
    const float* bt1 = (const float*)d_in[5];
    const float* m1  = (const float*)d_in[6];
    const float* v1  = (const float*)d_in[7];
    const float* W2  = (const float*)d_in[8];
    const float* b2  = (const float*)d_in[9];
    const float* g2  = (const float*)d_in[10];
    const float* bt2 = (const float*)d_in[11];
    const float* m2  = (const float*)d_in[12];
    const float* v2  = (const float*)d_in[13];
    const float* W3  = (const float*)d_in[14];
    const float* b3  = (const float*)d_in[15];
    const float* g3  = (const float*)d_in[16];
    const float* bt3 = (const float*)d_in[17];
    const float* m3  = (const float*)d_in[18];
    const float* v3  = (const float*)d_in[19];
    float* out = (float*)d_out;

    fold_kernel<<<1, 256>>>(W1,b1,g1,bt1,m1,v1, W2,b2,g2,bt2,m2,v2, W3,b3,g3,bt3,m3,v3);

    cudaFuncSetAttribute(pipe_kernel, cudaFuncAttributeMaxDynamicSharedMemorySize, SMEM_BYTES);
    pipe_kernel<<<GRID, TPB, SMEM_BYTES>>>(x, xc, out);
}